// round 2
// baseline (speedup 1.0000x reference)
#include <cuda_runtime.h>
#include <math.h>

#define SQ   512
#define BB   64
#define FIN  512
#define HH   512
#define G4   2048   // 4*H

// Scratch (static device arrays: allocation-guard safe)
__device__ float g_xg[(long long)SQ * BB * G4];   // input-projection gates [S, B, 4H]
__device__ float g_c [(long long)SQ * BB * HH];   // fallback c-state history

__device__ __forceinline__ float sig(float x) { return 1.0f / (1.0f + expf(-x)); }

// ---------------------------------------------------------------------------
// Kernel A: XG[m, j] = sum_k seq[m,k] * w_ih[j,k] + (b_ih[j] + b_hh[j])
// A = seq [32768, 512] row-major, W = w_ih [2048, 512] row-major (both K-contig)
// 128x128 tile, BK=8, 256 threads, 8x8 per thread.
// ---------------------------------------------------------------------------
__global__ __launch_bounds__(256)
void gemm_in(const float* __restrict__ A, const float* __restrict__ W,
             const float* __restrict__ bih, const float* __restrict__ bhh,
             float* __restrict__ C)
{
    __shared__ float As[8][132];
    __shared__ float Bs[8][132];

    const int tid  = threadIdx.x;
    const int tx   = tid & 15;
    const int ty   = tid >> 4;
    const int m0   = blockIdx.y * 128;
    const int n0   = blockIdx.x * 128;
    const int lrow = tid >> 1;
    const int lk4  = (tid & 1) * 4;

    const float* Aptr = A + (size_t)(m0 + lrow) * FIN + lk4;
    const float* Wptr = W + (size_t)(n0 + lrow) * FIN + lk4;

    float acc[8][8];
    #pragma unroll
    for (int i = 0; i < 8; i++)
        #pragma unroll
        for (int j = 0; j < 8; j++) acc[i][j] = 0.0f;

    float4 ra = *(const float4*)(Aptr);
    float4 rb = *(const float4*)(Wptr);

    for (int kb = 0; kb < 64; kb++) {
        As[lk4 + 0][lrow] = ra.x; As[lk4 + 1][lrow] = ra.y;
        As[lk4 + 2][lrow] = ra.z; As[lk4 + 3][lrow] = ra.w;
        Bs[lk4 + 0][lrow] = rb.x; Bs[lk4 + 1][lrow] = rb.y;
        Bs[lk4 + 2][lrow] = rb.z; Bs[lk4 + 3][lrow] = rb.w;
        __syncthreads();

        if (kb < 63) {
            ra = *(const float4*)(Aptr + (kb + 1) * 8);
            rb = *(const float4*)(Wptr + (kb + 1) * 8);
        }

        #pragma unroll
        for (int kk = 0; kk < 8; kk++) {
            float a[8], b[8];
            *(float4*)(a)     = *(const float4*)&As[kk][ty * 8];
            *(float4*)(a + 4) = *(const float4*)&As[kk][ty * 8 + 4];
            *(float4*)(b)     = *(const float4*)&Bs[kk][tx * 8];
            *(float4*)(b + 4) = *(const float4*)&Bs[kk][tx * 8 + 4];
            #pragma unroll
            for (int i = 0; i < 8; i++)
                #pragma unroll
                for (int j = 0; j < 8; j++)
                    acc[i][j] += a[i] * b[j];
        }
        __syncthreads();
    }

    float bias[8];
    #pragma unroll
    for (int j = 0; j < 8; j++) {
        int n = n0 + tx * 8 + j;
        bias[j] = bih[n] + bhh[n];
    }
    #pragma unroll
    for (int i = 0; i < 8; i++) {
        int m = m0 + ty * 8 + i;
        float4 o0 = make_float4(acc[i][0] + bias[0], acc[i][1] + bias[1],
                                acc[i][2] + bias[2], acc[i][3] + bias[3]);
        float4 o1 = make_float4(acc[i][4] + bias[4], acc[i][5] + bias[5],
                                acc[i][6] + bias[6], acc[i][7] + bias[7]);
        *(float4*)(C + (size_t)m * G4 + n0 + tx * 8)     = o0;
        *(float4*)(C + (size_t)m * G4 + n0 + tx * 8 + 4) = o1;
    }
}

// ---------------------------------------------------------------------------
// Kernel B: one LSTM time step.
// Block handles 4 h-indices (n0..n0+3) => 16 gate rows, ALL 64 batches, K=512.
// 256 threads = ks(4 K-quarters) x bg(16 batch-groups of 4) x nn(4 n-values).
// smem: sH[64][513] (h_prev), sW[16][513] (w_hh rows, row = nn*4+g), padded
// stride 513 => conflict-free scalar LDS. Reduce across K-quarters in smem,
// then fused gate activations + state update.
// ---------------------------------------------------------------------------
#define SH_STRIDE 513
#define STEP_SMEM ((64 * SH_STRIDE + 16 * SH_STRIDE) * 4)

__global__ __launch_bounds__(256)
void lstm_step(const float* __restrict__ xg_t,   // g_xg + t*B*4H
               const float* __restrict__ Whh,    // [2048, 512]
               const float* __restrict__ h_prev, // [64, 512]
               const float* __restrict__ c_prev, // [64, 512]
               float* __restrict__ h_out,
               float* __restrict__ c_out,
               int first)
{
    extern __shared__ float sm[];
    float* sH = sm;                     // 64 * 513
    float* sW = sm + 64 * SH_STRIDE;    // 16 * 513 (reused as reduce buffer)

    const int tid = threadIdx.x;
    const int ks  = tid >> 6;        // 0..3  K-quarter
    const int bg  = (tid >> 2) & 15; // 0..15 batch group (4 batches each)
    const int nn  = tid & 3;         // 0..3  n within block
    const int n0  = blockIdx.x * 4;

    float acc[4][4] = {};            // [bb][gate]

    if (!first) {
        // Stage h_prev -> sH[b][k] (coalesced global, conflict-free stores)
        #pragma unroll 4
        for (int i = 0; i < 32; i++) {
            int s  = tid + 256 * i;          // 0..8191
            int b  = s >> 7;
            int k4 = (s & 127) * 4;
            float4 v = *(const float4*)(h_prev + b * HH + k4);
            float* d = sH + b * SH_STRIDE + k4;
            d[0] = v.x; d[1] = v.y; d[2] = v.z; d[3] = v.w;
        }
        // Stage 16 w_hh rows -> sW[r][k], r = nn*4 + gate
        #pragma unroll 4
        for (int i = 0; i < 8; i++) {
            int s  = tid + 256 * i;          // 0..2047
            int r  = s >> 7;
            int k4 = (s & 127) * 4;
            int g  = r & 3;
            int nr = r >> 2;
            float4 v = *(const float4*)(Whh + (size_t)(g * HH + n0 + nr) * HH + k4);
            float* d = sW + r * SH_STRIDE + k4;
            d[0] = v.x; d[1] = v.y; d[2] = v.z; d[3] = v.w;
        }
        __syncthreads();

        const float* hr = sH + (bg * 4) * SH_STRIDE;
        const float* wr = sW + (nn * 4) * SH_STRIDE;
        const int kbeg = ks * 128;
        #pragma unroll 4
        for (int k = kbeg; k < kbeg + 128; k++) {
            float h0 = hr[k];
            float h1 = hr[SH_STRIDE + k];
            float h2 = hr[2 * SH_STRIDE + k];
            float h3 = hr[3 * SH_STRIDE + k];
            float w0 = wr[k];
            float w1 = wr[SH_STRIDE + k];
            float w2 = wr[2 * SH_STRIDE + k];
            float w3 = wr[3 * SH_STRIDE + k];
            acc[0][0] += h0 * w0; acc[0][1] += h0 * w1; acc[0][2] += h0 * w2; acc[0][3] += h0 * w3;
            acc[1][0] += h1 * w0; acc[1][1] += h1 * w1; acc[1][2] += h1 * w2; acc[1][3] += h1 * w3;
            acc[2][0] += h2 * w0; acc[2][1] += h2 * w1; acc[2][2] += h2 * w2; acc[2][3] += h2 * w3;
            acc[3][0] += h3 * w0; acc[3][1] += h3 * w1; acc[3][2] += h3 * w2; acc[3][3] += h3 * w3;
        }
        __syncthreads();  // done reading sW before reduce overwrites it
    }

    // Reduce across the 4 K-quarters via smem (stride 17: conflict-free)
    float* red = sW;  // 256*17 floats = 17KB, fits in sW region
    #pragma unroll
    for (int bb = 0; bb < 4; bb++)
        #pragma unroll
        for (int g = 0; g < 4; g++)
            red[tid * 17 + bb * 4 + g] = acc[bb][g];
    __syncthreads();

    if (tid < 64) {  // ks==0 threads: same (bg, nn) mapping
        const int bgl = tid >> 2;
        const int nnl = tid & 3;
        #pragma unroll
        for (int bb = 0; bb < 4; bb++) {
            float s0 = 0.f, s1 = 0.f, s2 = 0.f, s3 = 0.f;
            #pragma unroll
            for (int p = 0; p < 4; p++) {
                const float* rp = red + (tid + 64 * p) * 17 + bb * 4;
                s0 += rp[0]; s1 += rp[1]; s2 += rp[2]; s3 += rp[3];
            }
            const int b = bgl * 4 + bb;
            const int n = n0 + nnl;
            const size_t xb = (size_t)b * G4 + n;
            float pi = xg_t[xb]        + s0;   // gate order: i, f, g, o
            float pf = xg_t[xb + 512]  + s1;
            float pg = xg_t[xb + 1024] + s2;
            float po = xg_t[xb + 1536] + s3;
            float cp = first ? 0.f : c_prev[b * HH + n];
            float cn = sig(pf) * cp + sig(pi) * tanhf(pg);
            float hn = sig(po) * tanhf(cn);
            h_out[b * HH + n] = hn;
            c_out[b * HH + n] = cn;
        }
    }
}

// ---------------------------------------------------------------------------
// Host: one input GEMM + 512 step launches. hs region of d_out doubles as the
// h-state history; cs region (or g_c fallback) holds the c-state history.
// ---------------------------------------------------------------------------
extern "C" void kernel_launch(void* const* d_in, const int* in_sizes, int n_in,
                              void* d_out, int out_size)
{
    const float* seq = (const float*)d_in[0];
    const float* wih = (const float*)d_in[1];
    const float* whh = (const float*)d_in[2];
    const float* bih = (const float*)d_in[3];
    const float* bhh = (const float*)d_in[4];
    float* out = (float*)d_out;

    float *xg, *cscr;
    cudaGetSymbolAddress((void**)&xg, g_xg);
    cudaGetSymbolAddress((void**)&cscr, g_c);

    const size_t SBH = (size_t)SQ * BB * HH;       // 16,777,216
    float* cbase = ((size_t)out_size >= 2 * SBH) ? (out + SBH) : cscr;

    dim3 gg(G4 / 128, (SQ * BB) / 128);            // (16, 256)
    gemm_in<<<gg, 256>>>(seq, wih, bih, bhh, xg);

    cudaFuncSetAttribute(lstm_step, cudaFuncAttributeMaxDynamicSharedMemorySize,
                         STEP_SMEM);

    const size_t BH = (size_t)BB * HH;
    for (int t = 0; t < SQ; t++) {
        const float* hp = (t == 0) ? out   : out   + (size_t)(t - 1) * BH;
        const float* cp = (t == 0) ? cbase : cbase + (size_t)(t - 1) * BH;
        lstm_step<<<128, 256, STEP_SMEM>>>(
            xg + (size_t)t * BB * G4, whh, hp, cp,
            out + (size_t)t * BH, cbase + (size_t)t * BH, t == 0);
    }
}

// round 3
// speedup vs baseline: 1.5291x; 1.5291x over previous
#include <cuda_runtime.h>
#include <math.h>

#define SQ   512
#define BB   64
#define FIN  512
#define HH   512
#define G4   2048   // 4*H

typedef unsigned long long ull;

// Scratch (static device arrays: allocation-guard safe)
__device__ float g_xg[(long long)SQ * BB * G4];   // input-projection gates [S, B, 4H]
__device__ float g_c [(long long)SQ * BB * HH];   // fallback c-state history
__device__ int   g_bar[SQ];                       // per-step arrival counters

__device__ __forceinline__ float sig(float x) { return 1.0f / (1.0f + expf(-x)); }

// Packed fp32x2 FMA (sm_10x): d.lo += a.lo*b.lo ; d.hi += a.hi*b.hi (IEEE fp32 each lane)
__device__ __forceinline__ void ffma2(ull& d, ull a, ull b) {
    asm("fma.rn.f32x2 %0, %1, %2, %0;" : "+l"(d) : "l"(a), "l"(b));
}
__device__ __forceinline__ ull packf2(float x, float y) {
    ull d; asm("mov.b64 %0, {%1, %2};" : "=l"(d) : "f"(x), "f"(y)); return d;
}
__device__ __forceinline__ float2 unpackf2(ull v) {
    float2 r; asm("mov.b64 {%0, %1}, %2;" : "=f"(r.x), "=f"(r.y) : "l"(v)); return r;
}
__device__ __forceinline__ int ld_acq(const int* p) {
    int v; asm volatile("ld.acquire.gpu.global.s32 %0, [%1];" : "=r"(v) : "l"(p) : "memory");
    return v;
}

// ---------------------------------------------------------------------------
// bar_init: zero per-step barrier counters (runs every graph replay)
// ---------------------------------------------------------------------------
__global__ void bar_init() { g_bar[threadIdx.x] = 0; }

// ---------------------------------------------------------------------------
// Kernel A: XG[m, j] = sum_k seq[m,k] * w_ih[j,k] + (b_ih[j] + b_hh[j])
// 128x128 tile, BK=8, 256 threads, 8x8 per thread, f32x2-packed over m-pairs.
// ---------------------------------------------------------------------------
__global__ __launch_bounds__(256)
void gemm_in(const float* __restrict__ A, const float* __restrict__ W,
             const float* __restrict__ bih, const float* __restrict__ bhh,
             float* __restrict__ C)
{
    __shared__ float As[8][132];
    __shared__ float Bs[8][132];

    const int tid  = threadIdx.x;
    const int tx   = tid & 15;
    const int ty   = tid >> 4;
    const int m0   = blockIdx.y * 128;
    const int n0   = blockIdx.x * 128;
    const int lrow = tid >> 1;
    const int lk4  = (tid & 1) * 4;

    const float* Aptr = A + (size_t)(m0 + lrow) * FIN + lk4;
    const float* Wptr = W + (size_t)(n0 + lrow) * FIN + lk4;

    // acc2[i2][j]: packed pair (row 2*i2, row 2*i2+1) x col j
    ull acc2[4][8];
    #pragma unroll
    for (int i = 0; i < 4; i++)
        #pragma unroll
        for (int j = 0; j < 8; j++) acc2[i][j] = 0ULL;

    float4 ra = *(const float4*)(Aptr);
    float4 rb = *(const float4*)(Wptr);

    for (int kb = 0; kb < 64; kb++) {
        As[lk4 + 0][lrow] = ra.x; As[lk4 + 1][lrow] = ra.y;
        As[lk4 + 2][lrow] = ra.z; As[lk4 + 3][lrow] = ra.w;
        Bs[lk4 + 0][lrow] = rb.x; Bs[lk4 + 1][lrow] = rb.y;
        Bs[lk4 + 2][lrow] = rb.z; Bs[lk4 + 3][lrow] = rb.w;
        __syncthreads();

        if (kb < 63) {
            ra = *(const float4*)(Aptr + (kb + 1) * 8);
            rb = *(const float4*)(Wptr + (kb + 1) * 8);
        }

        #pragma unroll
        for (int kk = 0; kk < 8; kk++) {
            ulonglong2 a01 = *(const ulonglong2*)&As[kk][ty * 8];
            ulonglong2 a23 = *(const ulonglong2*)&As[kk][ty * 8 + 4];
            ull av[4] = {a01.x, a01.y, a23.x, a23.y};
            float4 b0 = *(const float4*)&Bs[kk][tx * 8];
            float4 b1 = *(const float4*)&Bs[kk][tx * 8 + 4];
            ull rbk[8];
            rbk[0] = packf2(b0.x, b0.x); rbk[1] = packf2(b0.y, b0.y);
            rbk[2] = packf2(b0.z, b0.z); rbk[3] = packf2(b0.w, b0.w);
            rbk[4] = packf2(b1.x, b1.x); rbk[5] = packf2(b1.y, b1.y);
            rbk[6] = packf2(b1.z, b1.z); rbk[7] = packf2(b1.w, b1.w);
            #pragma unroll
            for (int i2 = 0; i2 < 4; i2++)
                #pragma unroll
                for (int j = 0; j < 8; j++)
                    ffma2(acc2[i2][j], av[i2], rbk[j]);
        }
        __syncthreads();
    }

    float bias[8];
    #pragma unroll
    for (int j = 0; j < 8; j++) {
        int n = n0 + tx * 8 + j;
        bias[j] = bih[n] + bhh[n];
    }
    #pragma unroll
    for (int i2 = 0; i2 < 4; i2++) {
        float r0[8], r1[8];
        #pragma unroll
        for (int j = 0; j < 8; j++) {
            float2 v = unpackf2(acc2[i2][j]);
            r0[j] = v.x + bias[j];
            r1[j] = v.y + bias[j];
        }
        int m = m0 + ty * 8 + 2 * i2;
        float* p0 = C + (size_t)m * G4 + n0 + tx * 8;
        float* p1 = p0 + G4;
        *(float4*)(p0)     = make_float4(r0[0], r0[1], r0[2], r0[3]);
        *(float4*)(p0 + 4) = make_float4(r0[4], r0[5], r0[6], r0[7]);
        *(float4*)(p1)     = make_float4(r1[0], r1[1], r1[2], r1[3]);
        *(float4*)(p1 + 4) = make_float4(r1[4], r1[5], r1[6], r1[7]);
    }
}

// ---------------------------------------------------------------------------
// Kernel B: PERSISTENT recurrence. One launch runs all 512 steps with a
// software grid barrier (128 blocks, all resident: 1 block/SM by smem).
//
// Block bid owns 4 h-columns n0=4*bid (16 gate rows of w_hh, staged in smem
// ONCE). Threads: tid = ks*32 + bg*4 + nn  (ks: 8 K-chunks of 64; bg: 8 batch
// groups; nn: 4 n). Thread tile = 8 batches (b = bg + 8*bb) x 4 gates,
// f32x2-packed over k via LDS.128 (strides 516 => conflict-free h loads).
// c-state lives in a register (each (b,n) owned by one thread forever).
// ---------------------------------------------------------------------------
#define SWS 516
#define SHS 516
#define RED_S 36
#define SMEM_FLOATS (16 * SWS + 64 * SHS)
#define SMEM_BYTES  (SMEM_FLOATS * 4)

__global__ __launch_bounds__(256, 1)
void lstm_persist(const float* __restrict__ xg,
                  const float* __restrict__ Whh,
                  float* __restrict__ hout,    // [S][B][H] (output hs, doubles as h history)
                  float* __restrict__ cout)    // [S][B][H] (output cs)
{
    extern __shared__ float sm[];
    float* sW  = sm;                 // 16 x 516 (persistent across steps)
    float* sH  = sm + 16 * SWS;      // 64 x 516
    float* red = sH;                 // reduction buffer overlays sH (256 x 36)

    const int tid = threadIdx.x;
    const int ks  = tid >> 5;
    const int bg  = (tid >> 2) & 7;
    const int nn  = tid & 3;
    const int n0  = blockIdx.x * 4;

    // Stage the block's 16 w_hh rows once. Row r = nn*4 + g.
    #pragma unroll
    for (int i = 0; i < 8; i++) {
        int s  = tid + 256 * i;            // 0..2047 float4 units
        int r  = s >> 7;
        int k4 = (s & 127) * 4;
        int g  = r & 3;
        int nr = r >> 2;
        float4 v = *(const float4*)(Whh + (size_t)(g * HH + n0 + nr) * HH + k4);
        float* d = sW + r * SWS + k4;
        d[0] = v.x; d[1] = v.y; d[2] = v.z; d[3] = v.w;
    }
    __syncthreads();

    // This thread's persistent output coordinate + c register
    const int ob = tid >> 2;            // batch 0..63
    const int on = n0 + (tid & 3);      // h column
    float creg = 0.0f;

    const int kbeg = ks * 64;
    const float* wb = sW + (nn * 4) * SWS + kbeg;
    const float* hb = sH + bg * SHS + kbeg;

    for (int t = 0; t < SQ; t++) {
        float s0 = 0.f, s1 = 0.f, s2 = 0.f, s3 = 0.f;

        if (t > 0) {
            // Wait for all blocks to finish step t-1
            if (tid == 0) { while (ld_acq(&g_bar[t - 1]) < 128) {} }
            __syncthreads();

            // Stage h(t-1) -> sH
            const float* hp = hout + (size_t)(t - 1) * BB * HH;
            #pragma unroll
            for (int i = 0; i < 32; i++) {
                int s  = tid + 256 * i;
                int b  = s >> 7;
                int k4 = (s & 127) * 4;
                float4 v = *(const float4*)(hp + b * HH + k4);
                float* d = sH + b * SHS + k4;
                d[0] = v.x; d[1] = v.y; d[2] = v.z; d[3] = v.w;
            }
            __syncthreads();

            // 8 batches x 4 gates, f32x2-packed over k
            ull acc[8][4];
            #pragma unroll
            for (int bb = 0; bb < 8; bb++)
                #pragma unroll
                for (int g = 0; g < 4; g++) acc[bb][g] = 0ULL;

            #pragma unroll 4
            for (int k = 0; k < 64; k += 4) {
                ulonglong2 w0 = *(const ulonglong2*)(wb + k);
                ulonglong2 w1 = *(const ulonglong2*)(wb + SWS + k);
                ulonglong2 w2 = *(const ulonglong2*)(wb + 2 * SWS + k);
                ulonglong2 w3 = *(const ulonglong2*)(wb + 3 * SWS + k);
                #pragma unroll
                for (int bb = 0; bb < 8; bb++) {
                    ulonglong2 h = *(const ulonglong2*)(hb + bb * 8 * SHS + k);
                    ffma2(acc[bb][0], h.x, w0.x); ffma2(acc[bb][0], h.y, w0.y);
                    ffma2(acc[bb][1], h.x, w1.x); ffma2(acc[bb][1], h.y, w1.y);
                    ffma2(acc[bb][2], h.x, w2.x); ffma2(acc[bb][2], h.y, w2.y);
                    ffma2(acc[bb][3], h.x, w3.x); ffma2(acc[bb][3], h.y, w3.y);
                }
            }
            __syncthreads();   // done reading sH before overlay writes

            // Write partials: red[tid][bb] = float4(gates 0..3) for batch bg+8*bb
            float4* rp = (float4*)(red + tid * RED_S);
            #pragma unroll
            for (int bb = 0; bb < 8; bb++) {
                float2 a0 = unpackf2(acc[bb][0]);
                float2 a1 = unpackf2(acc[bb][1]);
                float2 a2 = unpackf2(acc[bb][2]);
                float2 a3 = unpackf2(acc[bb][3]);
                rp[bb] = make_float4(a0.x + a0.y, a1.x + a1.y,
                                     a2.x + a2.y, a3.x + a3.y);
            }
            __syncthreads();

            // Reduce across the 8 K-chunks for this thread's (ob, on)
            const int bgl = ob & 7, bbl = ob >> 3, nl = tid & 3;
            #pragma unroll
            for (int p = 0; p < 8; p++) {
                float4 v = *(const float4*)(red + (p * 32 + bgl * 4 + nl) * RED_S + bbl * 4);
                s0 += v.x; s1 += v.y; s2 += v.z; s3 += v.w;
            }
        }

        // Gate epilogue + state update (gate order: i, f, g, o)
        const float* xgt = xg + (size_t)t * BB * G4 + (size_t)ob * G4 + on;
        float pi = xgt[0]    + s0;
        float pf = xgt[512]  + s1;
        float pg = xgt[1024] + s2;
        float po = xgt[1536] + s3;
        float cn = sig(pf) * creg + sig(pi) * tanhf(pg);
        float hn = sig(po) * tanhf(cn);
        creg = cn;
        hout[(size_t)t * BB * HH + ob * HH + on] = hn;
        cout[(size_t)t * BB * HH + ob * HH + on] = cn;

        // Publish step t
        __threadfence();
        __syncthreads();
        if (tid == 0) atomicAdd(&g_bar[t], 1);
    }
}

// ---------------------------------------------------------------------------
// Host
// ---------------------------------------------------------------------------
extern "C" void kernel_launch(void* const* d_in, const int* in_sizes, int n_in,
                              void* d_out, int out_size)
{
    const float* seq = (const float*)d_in[0];
    const float* wih = (const float*)d_in[1];
    const float* whh = (const float*)d_in[2];
    const float* bih = (const float*)d_in[3];
    const float* bhh = (const float*)d_in[4];
    float* out = (float*)d_out;

    float *xg, *cscr;
    cudaGetSymbolAddress((void**)&xg, g_xg);
    cudaGetSymbolAddress((void**)&cscr, g_c);

    const size_t SBH = (size_t)SQ * BB * HH;
    float* cbase = ((size_t)out_size >= 2 * SBH) ? (out + SBH) : cscr;

    bar_init<<<1, SQ>>>();

    dim3 gg(G4 / 128, (SQ * BB) / 128);            // (16, 256)
    gemm_in<<<gg, 256>>>(seq, wih, bih, bhh, xg);

    cudaFuncSetAttribute(lstm_persist, cudaFuncAttributeMaxDynamicSharedMemorySize,
                         SMEM_BYTES);
    lstm_persist<<<128, 256, SMEM_BYTES>>>(xg, whh, out, cbase);
}